// round 1
// baseline (speedup 1.0000x reference)
#include <cuda_runtime.h>
#include <cstdint>

// Problem constants (image is [16, 1024, 1024, 1] fp32; 4 scales).
#define HW 1024
#define PLANE (HW * HW)          // 1048576
#define BMAX 16

// Ping-pong scratch for the low-pass images (allocation-free rule: __device__ globals).
static __device__ float g_lowA[BMAX * PLANE];
static __device__ float g_lowB[BMAX * PLANE];

__device__ __forceinline__ int reflect_idx(int i) {
    // jnp.pad mode='symmetric': -1 -> 0, -2 -> 1, N -> N-1, N+1 -> N-2
    if (i < 0)   i = -1 - i;
    if (i >= HW) i = 2 * HW - 1 - i;
    return i;
}

__device__ __forceinline__ float4 ld4_reflect(const float* __restrict__ row, int c) {
    if ((unsigned)c <= (unsigned)(HW - 4)) {
        return *reinterpret_cast<const float4*>(row + c);
    }
    float4 v;
    v.x = row[reflect_idx(c + 0)];
    v.y = row[reflect_idx(c + 1)];
    v.z = row[reflect_idx(c + 2)];
    v.w = row[reflect_idx(c + 3)];
    return v;
}

// One fused starlet scale:
//   low' = conv5x5_dilated(low, symmetric pad), coeff = (low - low') / norm
// Vertical pass: global -> smem (float4 coalesced row reads, y-reflection).
// Horizontal pass: smem -> registers (LDS.128 windows, conflict-free) -> STG.128.
//
// SRC: 0 = external input ptr, 1 = g_lowA, 2 = g_lowB
// DST: 0 = none (last scale), 1 = g_lowA, 2 = g_lowB
template<int DIL, int SRC, int DST>
__global__ __launch_bounds__(256)
void starlet_scale_kernel(const float* __restrict__ ext_in,
                          const float* __restrict__ norms,
                          int scale,
                          float* __restrict__ coeff_out)
{
    constexpr int TX  = 128;                   // output columns per block
    constexpr int TY  = 8;                     // output rows per block
    constexpr int PAD = (2 * DIL + 3) & ~3;    // x halo rounded to float4: 4,4,8,16
    constexpr int REG = TX + 2 * PAD;          // staged columns: 136,136,144,160
    constexpr int NG  = REG / 4;               // float4 groups per row
    constexpr int NGW = (DIL == 1) ? 3 : (DIL == 2) ? 3 : (DIL == 4) ? 5 : 9;
    constexpr int SMSTRIDE = REG + 4;          // keep rows 16B aligned, small pad

    __shared__ __align__(16) float sm[TY][SMSTRIDE];

    const int bx = blockIdx.x * TX;
    const int by = blockIdx.y * TY;
    const int b  = blockIdx.z;

    const float* src = (SRC == 0) ? ext_in : (SRC == 1 ? g_lowA : g_lowB);
    const float* simg = src + (size_t)b * PLANE;

    constexpr float w0 = 1.0f / 16.0f;
    constexpr float w1 = 1.0f / 4.0f;
    constexpr float w2 = 3.0f / 8.0f;

    // ---------------- Phase 1: vertical 5-tap (dilated) into smem ----------------
    const int tid = threadIdx.y * 32 + threadIdx.x;
    const int xs  = bx - PAD;

    for (int idx = tid; idx < TY * NG; idx += 256) {
        const int r = idx / NG;
        const int g = idx - r * NG;
        const int y = by + r;
        const int c = xs + 4 * g;

        const float* r0 = simg + (size_t)reflect_idx(y - 2 * DIL) * HW;
        const float* r1 = simg + (size_t)reflect_idx(y - DIL) * HW;
        const float* r2 = simg + (size_t)y * HW;
        const float* r3 = simg + (size_t)reflect_idx(y + DIL) * HW;
        const float* r4 = simg + (size_t)reflect_idx(y + 2 * DIL) * HW;

        const float4 a0 = ld4_reflect(r0, c);
        const float4 a1 = ld4_reflect(r1, c);
        const float4 a2 = ld4_reflect(r2, c);
        const float4 a3 = ld4_reflect(r3, c);
        const float4 a4 = ld4_reflect(r4, c);

        float4 s;
        s.x = w0 * (a0.x + a4.x) + w1 * (a1.x + a3.x) + w2 * a2.x;
        s.y = w0 * (a0.y + a4.y) + w1 * (a1.y + a3.y) + w2 * a2.y;
        s.z = w0 * (a0.z + a4.z) + w1 * (a1.z + a3.z) + w2 * a2.z;
        s.w = w0 * (a0.w + a4.w) + w1 * (a1.w + a3.w) + w2 * a2.w;

        *reinterpret_cast<float4*>(&sm[r][4 * g]) = s;
    }
    __syncthreads();

    // ---------------- Phase 2: horizontal 5-tap (dilated) from smem ----------------
    const int tx = threadIdx.x;
    const int ty = threadIdx.y;
    const int y  = by + ty;

    // Register window: aligned LDS.128 reads, conflict-free (16B stride across lanes).
    float win[4 * NGW];
    #pragma unroll
    for (int i = 0; i < NGW; i++) {
        const float4 v = *reinterpret_cast<const float4*>(&sm[ty][4 * (tx + i)]);
        win[4 * i + 0] = v.x;
        win[4 * i + 1] = v.y;
        win[4 * i + 2] = v.z;
        win[4 * i + 3] = v.w;
    }

    constexpr int O = PAD - 2 * DIL;   // 2 for DIL=1, else 0
    float4 low;
    {
        float r[4];
        #pragma unroll
        for (int j = 0; j < 4; j++) {
            r[j] = w0 * (win[O + j] + win[O + j + 4 * DIL])
                 + w1 * (win[O + j + DIL] + win[O + j + 3 * DIL])
                 + w2 *  win[O + j + 2 * DIL];
        }
        low.x = r[0]; low.y = r[1]; low.z = r[2]; low.w = r[3];
    }

    // Raw center values (same rows just read in phase 1 -> L1/L2 hit).
    const float4 raw = *reinterpret_cast<const float4*>(simg + (size_t)y * HW + bx + 4 * tx);

    const float inv = 1.0f / norms[scale];
    float4 cf;
    cf.x = (raw.x - low.x) * inv;
    cf.y = (raw.y - low.y) * inv;
    cf.z = (raw.z - low.z) * inv;
    cf.w = (raw.w - low.w) * inv;

    const size_t opix = ((size_t)b * HW + y) * HW + bx + 4 * tx;
    *reinterpret_cast<float4*>(coeff_out + opix) = cf;

    if (DST != 0) {
        float* dst = (DST == 1 ? g_lowA : g_lowB) + (size_t)b * PLANE;
        *reinterpret_cast<float4*>(dst + (size_t)y * HW + bx + 4 * tx) = low;
    }
}

extern "C" void kernel_launch(void* const* d_in, const int* in_sizes, int n_in,
                              void* d_out, int out_size)
{
    // Inputs per metadata order: image [16,1024,1024,1] f32, wav_norms [4] f32.
    int img_idx = 0, nrm_idx = 1;
    if (n_in >= 2 && in_sizes[0] == 4) { img_idx = 1; nrm_idx = 0; }

    const float* image = (const float*)d_in[img_idx];
    const float* norms = (const float*)d_in[nrm_idx];
    float* out = (float*)d_out;

    int B = in_sizes[img_idx] / PLANE;
    if (B < 1) B = 1;
    if (B > BMAX) B = BMAX;
    const size_t plane_all = (size_t)B * PLANE;

    dim3 block(32, 8);
    dim3 grid(HW / 128, HW / 8, B);

    // scale 0: image -> lowA
    starlet_scale_kernel<1, 0, 1><<<grid, block>>>(image, norms, 0, out + 0 * plane_all);
    // scale 1: lowA -> lowB
    starlet_scale_kernel<2, 1, 2><<<grid, block>>>(image, norms, 1, out + 1 * plane_all);
    // scale 2: lowB -> lowA
    starlet_scale_kernel<4, 2, 1><<<grid, block>>>(image, norms, 2, out + 2 * plane_all);
    // scale 3: lowA -> (none)
    starlet_scale_kernel<8, 1, 0><<<grid, block>>>(image, norms, 3, out + 3 * plane_all);
}

// round 2
// speedup vs baseline: 1.7166x; 1.7166x over previous
#include <cuda_runtime.h>
#include <cstdint>

#define HW 1024
#define PLANE (HW * HW)
#define BMAX 16

// Ping-pong scratch for the low-pass images (allocation-free rule).
static __device__ float g_lowA[BMAX * PLANE];
static __device__ float g_lowB[BMAX * PLANE];

__device__ __forceinline__ int refl(int i) {
    // jnp.pad 'symmetric': -1 -> 0, -2 -> 1, N -> N-1
    if (i < 0)    i = -1 - i;
    if (i >= HW)  i = 2 * HW - 1 - i;
    return i;
}

// One starlet scale, register-streaming formulation.
// Vertical dilated-by-D conv == plain 5-tap conv on each of D row-subsampled
// sub-images. Block = 256 threads = one full row of float4 columns.
// blockIdx.y = residue (0..D-1), blockIdx.x = strip of S sub-rows, blockIdx.z = batch.
// Each thread keeps a 5-deep float4 sliding window over its sub-image column:
// exactly 1 LDG.128 per produced row. Vertical result -> smem slab (R rows),
// then a horizontal 5-tap from smem (3-5 LDS.128), coeff uses the register-held
// raw center (window w[2]).
template<int D, int SRC, int DST>
__global__ __launch_bounds__(256)
void starlet_stream(const float* __restrict__ ext_in,
                    const float* __restrict__ norms,
                    int scale,
                    float* __restrict__ coeff_out)
{
    constexpr int S = 16;   // sub-rows per block
    constexpr int R = 8;    // sub-rows per smem slab
    constexpr float W0 = 1.0f / 16.0f;
    constexpr float W1 = 1.0f / 4.0f;
    constexpr float W2 = 3.0f / 8.0f;

    __shared__ __align__(16) float sm[R][HW + 4];

    const int t     = threadIdx.x;        // float4 column 0..255
    const int resid = blockIdx.y;         // residue class
    const int s0    = blockIdx.x * S;     // first sub-row of strip
    const int b     = blockIdx.z;

    const float* src  = (SRC == 0) ? ext_in : (SRC == 1 ? g_lowA : g_lowB);
    const float* simg = src + (size_t)b * PLANE;
    float* lowdst = (DST == 1) ? g_lowA : (DST == 2 ? g_lowB : nullptr);
    if (DST != 0) lowdst += (size_t)b * PLANE;

    const int x4 = 4 * t;
    const float inv = 1.0f / norms[scale];

    auto ldrow = [&](int s) -> float4 {
        const int f = refl(resid + D * s);   // full-image row, reflected
        return *reinterpret_cast<const float4*>(simg + (size_t)f * HW + x4);
    };

    // Window over sub-rows s-2 .. s+2 (for the first output s = s0).
    float4 w0v = ldrow(s0 - 2);
    float4 w1v = ldrow(s0 - 1);
    float4 w2v = ldrow(s0);
    float4 w3v = ldrow(s0 + 1);

    float4 raw[R];

    #pragma unroll
    for (int slab = 0; slab < S / R; slab++) {
        // ---- vertical: stream R rows, 1 LDG.128 each ----
        #pragma unroll
        for (int r = 0; r < R; r++) {
            const int s = s0 + slab * R + r;
            const float4 w4v = ldrow(s + 2);
            float4 v;
            v.x = W0 * (w0v.x + w4v.x) + W1 * (w1v.x + w3v.x) + W2 * w2v.x;
            v.y = W0 * (w0v.y + w4v.y) + W1 * (w1v.y + w3v.y) + W2 * w2v.y;
            v.z = W0 * (w0v.z + w4v.z) + W1 * (w1v.z + w3v.z) + W2 * w2v.z;
            v.w = W0 * (w0v.w + w4v.w) + W1 * (w1v.w + w3v.w) + W2 * w2v.w;
            raw[r] = w2v;                         // raw center for coeff
            *reinterpret_cast<float4*>(&sm[r][x4]) = v;
            w0v = w1v; w1v = w2v; w2v = w3v; w3v = w4v;
        }
        __syncthreads();

        // ---- horizontal: 5-tap dilated-by-D along x from smem ----
        #pragma unroll
        for (int r = 0; r < R; r++) {
            const int s  = s0 + slab * R + r;
            const int yf = resid + D * s;        // full-image output row
            float4 low;

            if constexpr (D >= 4) {
                constexpr int G = D / 4;         // tap offset in float4 groups
                if (t >= 2 * G && t <= 255 - 2 * G) {
                    const float4 a  = *reinterpret_cast<const float4*>(&sm[r][x4 - 8 * G]);
                    const float4 bb = *reinterpret_cast<const float4*>(&sm[r][x4 - 4 * G]);
                    const float4 c  = *reinterpret_cast<const float4*>(&sm[r][x4]);
                    const float4 d  = *reinterpret_cast<const float4*>(&sm[r][x4 + 4 * G]);
                    const float4 e  = *reinterpret_cast<const float4*>(&sm[r][x4 + 8 * G]);
                    low.x = W0 * (a.x + e.x) + W1 * (bb.x + d.x) + W2 * c.x;
                    low.y = W0 * (a.y + e.y) + W1 * (bb.y + d.y) + W2 * c.y;
                    low.z = W0 * (a.z + e.z) + W1 * (bb.z + d.z) + W2 * c.z;
                    low.w = W0 * (a.w + e.w) + W1 * (bb.w + d.w) + W2 * c.w;
                } else {
                    float lo[4];
                    #pragma unroll
                    for (int j = 0; j < 4; j++) {
                        const int e0 = x4 + j;
                        auto g = [&](int m) -> float {
                            int e = e0 + m;
                            if (e < 0)    e = -1 - e;
                            if (e >= HW)  e = 2 * HW - 1 - e;
                            return sm[r][e];
                        };
                        lo[j] = W0 * (g(-2 * D) + g(2 * D))
                              + W1 * (g(-D) + g(D)) + W2 * g(0);
                    }
                    low.x = lo[0]; low.y = lo[1]; low.z = lo[2]; low.w = lo[3];
                }
            } else {
                if (t >= 1 && t <= 254) {
                    float fl[12];
                    *reinterpret_cast<float4*>(&fl[0]) = *reinterpret_cast<const float4*>(&sm[r][x4 - 4]);
                    *reinterpret_cast<float4*>(&fl[4]) = *reinterpret_cast<const float4*>(&sm[r][x4]);
                    *reinterpret_cast<float4*>(&fl[8]) = *reinterpret_cast<const float4*>(&sm[r][x4 + 4]);
                    float lo[4];
                    #pragma unroll
                    for (int j = 0; j < 4; j++) {
                        lo[j] = W0 * (fl[4 + j - 2 * D] + fl[4 + j + 2 * D])
                              + W1 * (fl[4 + j - D]     + fl[4 + j + D])
                              + W2 *  fl[4 + j];
                    }
                    low.x = lo[0]; low.y = lo[1]; low.z = lo[2]; low.w = lo[3];
                } else {
                    float lo[4];
                    #pragma unroll
                    for (int j = 0; j < 4; j++) {
                        const int e0 = x4 + j;
                        auto g = [&](int m) -> float {
                            int e = e0 + m;
                            if (e < 0)    e = -1 - e;
                            if (e >= HW)  e = 2 * HW - 1 - e;
                            return sm[r][e];
                        };
                        lo[j] = W0 * (g(-2 * D) + g(2 * D))
                              + W1 * (g(-D) + g(D)) + W2 * g(0);
                    }
                    low.x = lo[0]; low.y = lo[1]; low.z = lo[2]; low.w = lo[3];
                }
            }

            float4 cf;
            cf.x = (raw[r].x - low.x) * inv;
            cf.y = (raw[r].y - low.y) * inv;
            cf.z = (raw[r].z - low.z) * inv;
            cf.w = (raw[r].w - low.w) * inv;

            const size_t o = ((size_t)b * HW + yf) * HW + x4;
            *reinterpret_cast<float4*>(coeff_out + o) = cf;
            if (DST != 0) {
                *reinterpret_cast<float4*>(lowdst + (size_t)yf * HW + x4) = low;
            }
        }
        __syncthreads();
    }
}

extern "C" void kernel_launch(void* const* d_in, const int* in_sizes, int n_in,
                              void* d_out, int out_size)
{
    int img_idx = 0, nrm_idx = 1;
    if (n_in >= 2 && in_sizes[0] == 4) { img_idx = 1; nrm_idx = 0; }

    const float* image = (const float*)d_in[img_idx];
    const float* norms = (const float*)d_in[nrm_idx];
    float* out = (float*)d_out;

    int B = in_sizes[img_idx] / PLANE;
    if (B < 1) B = 1;
    if (B > BMAX) B = BMAX;
    const size_t plane_all = (size_t)B * PLANE;

    const dim3 block(256);
    // grid: x = strips of 16 sub-rows, y = D residues, z = batch
    const dim3 g1(HW / (1 * 16), 1, B);
    const dim3 g2(HW / (2 * 16), 2, B);
    const dim3 g4(HW / (4 * 16), 4, B);
    const dim3 g8(HW / (8 * 16), 8, B);

    starlet_stream<1, 0, 1><<<g1, block>>>(image, norms, 0, out + 0 * plane_all);
    starlet_stream<2, 1, 2><<<g2, block>>>(image, norms, 1, out + 1 * plane_all);
    starlet_stream<4, 2, 1><<<g4, block>>>(image, norms, 2, out + 2 * plane_all);
    starlet_stream<8, 1, 0><<<g8, block>>>(image, norms, 3, out + 3 * plane_all);
}